// round 8
// baseline (speedup 1.0000x reference)
#include <cuda_runtime.h>
#include <math.h>
#include <stdint.h>

#define BB 16
#define DD 2048
#define NH 32
#define NKV 8
#define HDIM 64
#define GRP 4
#define TSEQ 4096
#define HIDDEN 5632
#define KVD 512
#define NSPLIT 32
#define TCHUNK 128

// ---------------- scratch ----------------
__device__ float g_xn[BB * DD];
__device__ float g_q[BB * DD];
__device__ float g_k[BB * KVD];
__device__ float g_v[BB * KVD];
__device__ float g_attn[BB * DD];
__device__ float g_h[BB * DD];
__device__ float g_hn[BB * DD];
__device__ float g_ff1[BB * HIDDEN];
__device__ float g_ff2[BB * DD];
__device__ float g_po[BB * NKV * NSPLIT * GRP * HDIM];
__device__ float g_pl[BB * NKV * NSPLIT * GRP];

__device__ __forceinline__ float warp_sum(float v) {
    v += __shfl_down_sync(0xffffffffu, v, 16);
    v += __shfl_down_sync(0xffffffffu, v, 8);
    v += __shfl_down_sync(0xffffffffu, v, 4);
    v += __shfl_down_sync(0xffffffffu, v, 2);
    v += __shfl_down_sync(0xffffffffu, v, 1);
    return v;
}

// ---------------- GEMV core: 8 rows/block, R=4, 4 K-quarters ----------------
// warp w: row-group rg=w&1 (4 rows), K-quarter kq=w>>1.
__device__ __forceinline__ bool gemv8_core(const float* __restrict__ A,
                                           const float* __restrict__ W,
                                           int K, int row0, int tid,
                                           int* pb, int* prr, float* pv) {
    __shared__ float s_part[8][16][4];
    int lane = tid & 31, w = tid >> 5;
    int rg = w & 1, kq = w >> 1;
    int o0 = row0 + rg * 4;
    int KQ = K >> 4;                    // float4 chunks per quarter
    int c0 = kq * KQ, c1 = c0 + KQ;
    const float4* w0 = (const float4*)(W + (size_t)(o0 + 0) * K);
    const float4* w1 = (const float4*)(W + (size_t)(o0 + 1) * K);
    const float4* w2 = (const float4*)(W + (size_t)(o0 + 2) * K);
    const float4* w3 = (const float4*)(W + (size_t)(o0 + 3) * K);

    float acc[16][4];
#pragma unroll
    for (int b = 0; b < 16; b++)
#pragma unroll
        for (int r = 0; r < 4; r++) acc[b][r] = 0.f;

    int c = c0 + lane;
    // main loop: 2 c-chunks in flight, weight loads front-batched
    for (; c + 32 < c1; c += 64) {
        float4 wv[2][4];
#pragma unroll
        for (int u = 0; u < 2; u++) {
            wv[u][0] = __ldcs(w0 + c + u * 32);
            wv[u][1] = __ldcs(w1 + c + u * 32);
            wv[u][2] = __ldcs(w2 + c + u * 32);
            wv[u][3] = __ldcs(w3 + c + u * 32);
        }
#pragma unroll
        for (int u = 0; u < 2; u++)
#pragma unroll
            for (int b = 0; b < 16; b++) {
                float4 xv = ((const float4*)(A + (size_t)b * K))[c + u * 32];
#pragma unroll
                for (int r = 0; r < 4; r++)
                    acc[b][r] += wv[u][r].x * xv.x + wv[u][r].y * xv.y +
                                 wv[u][r].z * xv.z + wv[u][r].w * xv.w;
            }
    }
    for (; c < c1; c += 32) {
        float4 wv[4];
        wv[0] = __ldcs(w0 + c); wv[1] = __ldcs(w1 + c);
        wv[2] = __ldcs(w2 + c); wv[3] = __ldcs(w3 + c);
#pragma unroll
        for (int b = 0; b < 16; b++) {
            float4 xv = ((const float4*)(A + (size_t)b * K))[c];
#pragma unroll
            for (int r = 0; r < 4; r++)
                acc[b][r] += wv[r].x * xv.x + wv[r].y * xv.y +
                             wv[r].z * xv.z + wv[r].w * xv.w;
        }
    }
#pragma unroll
    for (int b = 0; b < 16; b++)
#pragma unroll
        for (int r = 0; r < 4; r++) {
            float v = warp_sum(acc[b][r]);
            if (lane == 0) s_part[w][b][r] = v;
        }
    __syncthreads();
    if (tid < 128) {
        int b = tid >> 3, rr = tid & 7;
        int rg2 = rr >> 2, r2 = rr & 3;
        *pb = b; *prr = rr;
        *pv = s_part[rg2][b][r2] + s_part[2 + rg2][b][r2] +
              s_part[4 + rg2][b][r2] + s_part[6 + rg2][b][r2];
        return true;
    }
    return false;
}

// ---------------- rmsnorm ----------------
__global__ void rmsnorm_x_kernel(const float* __restrict__ x,
                                 const float* __restrict__ w) {
    int b = blockIdx.x;
    const float* xr = x + (size_t)b * DD;
    float s = 0.f;
    for (int i = threadIdx.x; i < DD; i += 256) { float v = xr[i]; s += v * v; }
    for (int off = 16; off; off >>= 1) s += __shfl_xor_sync(0xffffffffu, s, off);
    __shared__ float red[8];
    int lane = threadIdx.x & 31, wid = threadIdx.x >> 5;
    if (lane == 0) red[wid] = s;
    __syncthreads();
    if (threadIdx.x == 0) {
        float t = 0.f;
#pragma unroll
        for (int i = 0; i < 8; i++) t += red[i];
        red[0] = rsqrtf(t * (1.0f / DD) + 1e-6f);
    }
    __syncthreads();
    float inv = red[0];
    float* orow = g_xn + (size_t)b * DD;
    for (int i = threadIdx.x; i < DD; i += 256) orow[i] = xr[i] * inv * w[i];
}

__global__ void rmsnorm_h_kernel(const float* __restrict__ w) {
    int b = blockIdx.x;
    const float* xr = g_h + (size_t)b * DD;
    float s = 0.f;
    for (int i = threadIdx.x; i < DD; i += 256) { float v = xr[i]; s += v * v; }
    for (int off = 16; off; off >>= 1) s += __shfl_xor_sync(0xffffffffu, s, off);
    __shared__ float red[8];
    int lane = threadIdx.x & 31, wid = threadIdx.x >> 5;
    if (lane == 0) red[wid] = s;
    __syncthreads();
    if (threadIdx.x == 0) {
        float t = 0.f;
#pragma unroll
        for (int i = 0; i < 8; i++) t += red[i];
        red[0] = rsqrtf(t * (1.0f / DD) + 1e-6f);
    }
    __syncthreads();
    float inv = red[0];
    float* orow = g_hn + (size_t)b * DD;
    for (int i = threadIdx.x; i < DD; i += 256) orow[i] = xr[i] * inv * w[i];
}

// ---------------- GEMV kernels ----------------
__global__ __launch_bounds__(256) void gemv_qkv_kernel(
    const float* __restrict__ wq, const float* __restrict__ wk,
    const float* __restrict__ wv) {
    int row0 = blockIdx.x * 8;
    const float* Wm; int wrow0;
    if (row0 < 2048)      { Wm = wq; wrow0 = row0; }
    else if (row0 < 2560) { Wm = wk; wrow0 = row0 - 2048; }
    else                  { Wm = wv; wrow0 = row0 - 2560; }
    int b, rr; float v;
    if (gemv8_core(g_xn, Wm, DD, wrow0, threadIdx.x, &b, &rr, &v)) {
        int row = wrow0 + rr;
        if (row0 < 2048)      g_q[(size_t)b * DD + row] = v;
        else if (row0 < 2560) g_k[(size_t)b * KVD + row] = v;
        else                  g_v[(size_t)b * KVD + row] = v;
    }
}

__global__ __launch_bounds__(256) void gemv_wo_kernel(
    const float* __restrict__ wo, const float* __restrict__ x) {
    int row0 = blockIdx.x * 8;
    int b, rr; float v;
    if (gemv8_core(g_attn, wo, DD, row0, threadIdx.x, &b, &rr, &v)) {
        int row = row0 + rr;
        g_h[(size_t)b * DD + row] = v + x[(size_t)b * DD + row];
    }
}

__global__ __launch_bounds__(256) void gemv_w1_kernel(const float* __restrict__ w1) {
    int row0 = blockIdx.x * 8;
    int b, rr; float v;
    if (gemv8_core(g_hn, w1, DD, row0, threadIdx.x, &b, &rr, &v)) {
        int row = row0 + rr;
        g_ff1[(size_t)b * HIDDEN + row] = v / (1.0f + __expf(-v));
    }
}

__global__ __launch_bounds__(256) void gemv_w2_kernel(const float* __restrict__ w2) {
    int row0 = blockIdx.x * 8;
    int b, rr; float v;
    if (gemv8_core(g_ff1, w2, HIDDEN, row0, threadIdx.x, &b, &rr, &v)) {
        int row = row0 + rr;
        g_ff2[(size_t)b * DD + row] = v;
    }
}

__global__ __launch_bounds__(256) void gemv_w3fin_kernel(
    const float* __restrict__ w3, float* __restrict__ out) {
    int row0 = blockIdx.x * 8;
    int b, rr; float v;
    if (gemv8_core(g_hn, w3, DD, row0, threadIdx.x, &b, &rr, &v)) {
        int row = row0 + rr;
        out[(size_t)b * DD + row] =
            g_h[(size_t)b * DD + row] + g_ff2[(size_t)b * DD + row] + v;
    }
}

// ---------------- rope ----------------
__global__ void rope_kernel(const float* __restrict__ cosv,
                            const float* __restrict__ sinv) {
    int idx = blockIdx.x * 256 + threadIdx.x;
    if (idx >= BB * 48 * 32) return;
    int b = idx / (48 * 32);
    int r = idx % (48 * 32);
    int head = r >> 5;
    int i = r & 31;
    float c = cosv[i], s = sinv[i];
    float* ptr;
    if (head < 32)      ptr = g_q + (size_t)b * DD  + head * 64;
    else if (head < 40) ptr = g_k + (size_t)b * KVD + (head - 32) * 64;
    else                ptr = g_v + (size_t)b * KVD + (head - 40) * 64;
    float x0 = ptr[2 * i], x1 = ptr[2 * i + 1];
    ptr[2 * i]     = x0 * c - x1 * s;
    ptr[2 * i + 1] = x0 * s + x1 * c;
}

// ---------------- fused attention split kernel ----------------
// Single pass over t: score -> exp -> denominator + e*V accumulate.
// lane: c = lane&7 (d-slice of 8), p = lane>>3 (t within warp group of 4).
__global__ __launch_bounds__(256) void attn_split_kernel(
    const float* __restrict__ cache_k, const float* __restrict__ cache_v) {
    int blk = blockIdx.x;
    int pair = blk / NSPLIT, split = blk % NSPLIT;
    int b = pair >> 3, kv = pair & 7;
    int t0 = split * TCHUNK;
    int tid = threadIdx.x, lane = tid & 31, wid = tid >> 5;

    __shared__ float q_s[4][64];
    __shared__ float o_w[8][4][64];      // [warp][g][d]
    __shared__ float red[4][8];

    { // load + scale q
        int g = tid >> 6, d = tid & 63;
        q_s[g][d] = g_q[(size_t)b * DD + (kv * 4 + g) * 64 + d] * 0.125f;
    }
    __syncthreads();

    int c = lane & 7, p = lane >> 3;
    float qr[4][8];
#pragma unroll
    for (int g = 0; g < 4; g++)
#pragma unroll
        for (int j = 0; j < 8; j++) qr[g][j] = q_s[g][c * 8 + j];

    const float* kbase = cache_k + ((size_t)b * TSEQ * NKV + kv) * HDIM;
    const float* vbase = cache_v + ((size_t)b * TSEQ * NKV + kv) * HDIM;
    const float* knew  = g_k + (size_t)(b * NKV + kv) * HDIM;
    const float* vnew  = g_v + (size_t)(b * NKV + kv) * HDIM;

    float oacc[4][8];
#pragma unroll
    for (int g = 0; g < 4; g++)
#pragma unroll
        for (int j = 0; j < 8; j++) oacc[g][j] = 0.f;
    float esum[4] = {0.f, 0.f, 0.f, 0.f};

#pragma unroll 2
    for (int it = 0; it < TCHUNK / 32; it++) {
        int tl = it * 32 + wid * 4 + p;
        int t = t0 + tl;
        bool last = (t == TSEQ - 1);
        const float* krow = last ? knew : (kbase + (size_t)t * KVD);
        const float* vrow = last ? vnew : (vbase + (size_t)t * KVD);
        // issue both streams' loads up front
        float4 k0 = __ldcs(((const float4*)krow) + c * 2);
        float4 k1 = __ldcs(((const float4*)krow) + c * 2 + 1);
        float4 v0 = __ldcs(((const float4*)vrow) + c * 2);
        float4 v1 = __ldcs(((const float4*)vrow) + c * 2 + 1);
        float kv8[8] = {k0.x, k0.y, k0.z, k0.w, k1.x, k1.y, k1.z, k1.w};
        float s[4];
#pragma unroll
        for (int g = 0; g < 4; g++) {
            float a = 0.f;
#pragma unroll
            for (int j = 0; j < 8; j++) a += qr[g][j] * kv8[j];
            s[g] = a;
        }
#pragma unroll
        for (int off = 1; off <= 4; off <<= 1) {
            s[0] += __shfl_xor_sync(0xffffffffu, s[0], off);
            s[1] += __shfl_xor_sync(0xffffffffu, s[1], off);
            s[2] += __shfl_xor_sync(0xffffffffu, s[2], off);
            s[3] += __shfl_xor_sync(0xffffffffu, s[3], off);
        }
        float e[4];
#pragma unroll
        for (int g = 0; g < 4; g++) e[g] = __expf(s[g]);
#pragma unroll
        for (int g = 0; g < 4; g++) esum[g] += e[g];
        float v8[8] = {v0.x, v0.y, v0.z, v0.w, v1.x, v1.y, v1.z, v1.w};
#pragma unroll
        for (int g = 0; g < 4; g++)
#pragma unroll
            for (int j = 0; j < 8; j++) oacc[g][j] += e[g] * v8[j];
    }

    // reduce oacc across the 4 t-partitions (p) within the warp
#pragma unroll
    for (int g = 0; g < 4; g++)
#pragma unroll
        for (int j = 0; j < 8; j++) {
            oacc[g][j] += __shfl_xor_sync(0xffffffffu, oacc[g][j], 8);
            oacc[g][j] += __shfl_xor_sync(0xffffffffu, oacc[g][j], 16);
        }
    if (p == 0) {
#pragma unroll
        for (int g = 0; g < 4; g++)
#pragma unroll
            for (int j = 0; j < 8; j++) o_w[wid][g][c * 8 + j] = oacc[g][j];
    }
    // esum: every lane counted each t once per 8 lanes -> warp total / 8
#pragma unroll
    for (int g = 0; g < 4; g++) {
        esum[g] = warp_sum(esum[g]);
        if (lane == 0) red[g][wid] = esum[g] * 0.125f;
    }
    __syncthreads();
    if (tid < 4) {
        float s = 0.f;
#pragma unroll
        for (int w = 0; w < 8; w++) s += red[tid][w];
        g_pl[blk * 4 + tid] = s;
    }
    {
        int g = tid >> 6, d = tid & 63;
        float sum = 0.f;
#pragma unroll
        for (int w = 0; w < 8; w++) sum += o_w[w][g][d];
        g_po[(size_t)blk * 256 + g * 64 + d] = sum;
    }
}

// combine split partials (pure sums — no max rescale needed)
__global__ __launch_bounds__(256) void attn_reduce_kernel() {
    int pair = blockIdx.x;
    int b = pair >> 3, kv = pair & 7;
    int tid = threadIdx.x, g = tid >> 6, d = tid & 63;
    float l = 0.f, o = 0.f;
#pragma unroll
    for (int s = 0; s < NSPLIT; s++) {
        int bs = pair * NSPLIT + s;
        l += g_pl[bs * 4 + g];
        o += g_po[(size_t)bs * 256 + g * 64 + d];
    }
    g_attn[(size_t)b * DD + (kv * 4 + g) * 64 + d] = o / l;
}

// ---------------- launch ----------------
extern "C" void kernel_launch(void* const* d_in, const int* in_sizes, int n_in,
                              void* d_out, int out_size) {
    const float* x         = (const float*)d_in[0];
    const float* freqs_cos = (const float*)d_in[1];
    const float* freqs_sin = (const float*)d_in[2];
    const float* cache_k   = (const float*)d_in[3];
    const float* cache_v   = (const float*)d_in[4];
    const float* wq_w      = (const float*)d_in[5];
    const float* wk_w      = (const float*)d_in[6];
    const float* wv_w      = (const float*)d_in[7];
    const float* wo_w      = (const float*)d_in[8];
    const float* w1_w      = (const float*)d_in[9];
    const float* w2_w      = (const float*)d_in[10];
    const float* w3_w      = (const float*)d_in[11];
    const float* attn_nw   = (const float*)d_in[12];
    const float* ffn_nw    = (const float*)d_in[13];
    float* out = (float*)d_out;

    rmsnorm_x_kernel<<<BB, 256>>>(x, attn_nw);
    gemv_qkv_kernel<<<3072 / 8, 256>>>(wq_w, wk_w, wv_w);
    rope_kernel<<<(BB * 48 * 32 + 255) / 256, 256>>>(freqs_cos, freqs_sin);
    attn_split_kernel<<<BB * NKV * NSPLIT, 256>>>(cache_k, cache_v);
    attn_reduce_kernel<<<BB * NKV, 256>>>();
    gemv_wo_kernel<<<DD / 8, 256>>>(wo_w, x);
    rmsnorm_h_kernel<<<BB, 256>>>(ffn_nw);
    gemv_w1_kernel<<<HIDDEN / 8, 256>>>(w1_w);
    gemv_w2_kernel<<<DD / 8, 256>>>(w2_w);
    gemv_w3fin_kernel<<<DD / 8, 256>>>(w3_w, out);
}

// round 9
// speedup vs baseline: 1.0447x; 1.0447x over previous
#include <cuda_runtime.h>
#include <math.h>
#include <stdint.h>

#define BB 16
#define DD 2048
#define NH 32
#define NKV 8
#define HDIM 64
#define GRP 4
#define TSEQ 4096
#define HIDDEN 5632
#define KVD 512
#define NSPLIT 64
#define TCHUNK 64

// ---------------- scratch ----------------
__device__ float g_xn[BB * DD];
__device__ float g_q[BB * DD];
__device__ float g_k[BB * KVD];
__device__ float g_v[BB * KVD];
__device__ float g_attn[BB * DD];
__device__ float g_h[BB * DD];
__device__ float g_hn[BB * DD];
__device__ float g_ff1[BB * HIDDEN];
__device__ float g_ff2[BB * DD];
__device__ float g_po[BB * NKV * NSPLIT * GRP * HDIM];   // 8 MB
__device__ float g_pl[BB * NKV * NSPLIT * GRP];

__device__ __forceinline__ float warp_sum(float v) {
    v += __shfl_down_sync(0xffffffffu, v, 16);
    v += __shfl_down_sync(0xffffffffu, v, 8);
    v += __shfl_down_sync(0xffffffffu, v, 4);
    v += __shfl_down_sync(0xffffffffu, v, 2);
    v += __shfl_down_sync(0xffffffffu, v, 1);
    return v;
}

// ---------------- GEMV core v3: 4 rows/block, 8 batches/warp, 4 K-quarters --
// warp w: bh = w&1 (batches bh*8..+7), kq = w>>1 (K quarter). acc[8][4]=32 regs.
// Valid results for tid<64: b = tid>>2, r = tid&3.
__device__ __forceinline__ bool gemv4_core(const float* __restrict__ A,
                                           const float* __restrict__ W,
                                           int K, int row0, int tid,
                                           int* pb, int* pr, float* pv) {
    __shared__ float s_part[8][8][4];
    int lane = tid & 31, w = tid >> 5;
    int bh = w & 1, kq = w >> 1;
    const float* Ab = A + (size_t)bh * 8 * K;
    int KQ = K >> 4;                    // float4 chunks per quarter
    int c0 = kq * KQ, c1 = c0 + KQ;
    const float4* w0 = (const float4*)(W + (size_t)(row0 + 0) * K);
    const float4* w1 = (const float4*)(W + (size_t)(row0 + 1) * K);
    const float4* w2 = (const float4*)(W + (size_t)(row0 + 2) * K);
    const float4* w3 = (const float4*)(W + (size_t)(row0 + 3) * K);

    float acc[8][4];
#pragma unroll
    for (int b = 0; b < 8; b++)
#pragma unroll
        for (int r = 0; r < 4; r++) acc[b][r] = 0.f;

    int c = c0 + lane;
    for (; c + 32 < c1; c += 64) {
        float4 wv[2][4];
#pragma unroll
        for (int u = 0; u < 2; u++) {
            wv[u][0] = __ldcs(w0 + c + u * 32);
            wv[u][1] = __ldcs(w1 + c + u * 32);
            wv[u][2] = __ldcs(w2 + c + u * 32);
            wv[u][3] = __ldcs(w3 + c + u * 32);
        }
#pragma unroll
        for (int u = 0; u < 2; u++)
#pragma unroll
            for (int b = 0; b < 8; b++) {
                float4 xv = ((const float4*)(Ab + (size_t)b * K))[c + u * 32];
#pragma unroll
                for (int r = 0; r < 4; r++)
                    acc[b][r] += wv[u][r].x * xv.x + wv[u][r].y * xv.y +
                                 wv[u][r].z * xv.z + wv[u][r].w * xv.w;
            }
    }
    for (; c < c1; c += 32) {
        float4 wv[4];
        wv[0] = __ldcs(w0 + c); wv[1] = __ldcs(w1 + c);
        wv[2] = __ldcs(w2 + c); wv[3] = __ldcs(w3 + c);
#pragma unroll
        for (int b = 0; b < 8; b++) {
            float4 xv = ((const float4*)(Ab + (size_t)b * K))[c];
#pragma unroll
            for (int r = 0; r < 4; r++)
                acc[b][r] += wv[r].x * xv.x + wv[r].y * xv.y +
                             wv[r].z * xv.z + wv[r].w * xv.w;
        }
    }
#pragma unroll
    for (int b = 0; b < 8; b++)
#pragma unroll
        for (int r = 0; r < 4; r++) {
            float v = warp_sum(acc[b][r]);
            if (lane == 0) s_part[w][b][r] = v;
        }
    __syncthreads();
    if (tid < 64) {
        int b = tid >> 2, r = tid & 3;
        int bh2 = b >> 3, b8 = b & 7;
        *pb = b; *pr = r;
        *pv = s_part[0 * 2 + bh2][b8][r] + s_part[1 * 2 + bh2][b8][r] +
              s_part[2 * 2 + bh2][b8][r] + s_part[3 * 2 + bh2][b8][r];
        return true;
    }
    return false;
}

// ---------------- rmsnorm ----------------
__global__ void rmsnorm_x_kernel(const float* __restrict__ x,
                                 const float* __restrict__ w) {
    int b = blockIdx.x;
    const float* xr = x + (size_t)b * DD;
    float s = 0.f;
    for (int i = threadIdx.x; i < DD; i += 256) { float v = xr[i]; s += v * v; }
    for (int off = 16; off; off >>= 1) s += __shfl_xor_sync(0xffffffffu, s, off);
    __shared__ float red[8];
    int lane = threadIdx.x & 31, wid = threadIdx.x >> 5;
    if (lane == 0) red[wid] = s;
    __syncthreads();
    if (threadIdx.x == 0) {
        float t = 0.f;
#pragma unroll
        for (int i = 0; i < 8; i++) t += red[i];
        red[0] = rsqrtf(t * (1.0f / DD) + 1e-6f);
    }
    __syncthreads();
    float inv = red[0];
    float* orow = g_xn + (size_t)b * DD;
    for (int i = threadIdx.x; i < DD; i += 256) orow[i] = xr[i] * inv * w[i];
}

__global__ void rmsnorm_h_kernel(const float* __restrict__ w) {
    int b = blockIdx.x;
    const float* xr = g_h + (size_t)b * DD;
    float s = 0.f;
    for (int i = threadIdx.x; i < DD; i += 256) { float v = xr[i]; s += v * v; }
    for (int off = 16; off; off >>= 1) s += __shfl_xor_sync(0xffffffffu, s, off);
    __shared__ float red[8];
    int lane = threadIdx.x & 31, wid = threadIdx.x >> 5;
    if (lane == 0) red[wid] = s;
    __syncthreads();
    if (threadIdx.x == 0) {
        float t = 0.f;
#pragma unroll
        for (int i = 0; i < 8; i++) t += red[i];
        red[0] = rsqrtf(t * (1.0f / DD) + 1e-6f);
    }
    __syncthreads();
    float inv = red[0];
    float* orow = g_hn + (size_t)b * DD;
    for (int i = threadIdx.x; i < DD; i += 256) orow[i] = xr[i] * inv * w[i];
}

// ---------------- qkv GEMV with fused RoPE ----------------
__global__ __launch_bounds__(256) void gemv_qkv_kernel(
    const float* __restrict__ wq, const float* __restrict__ wk,
    const float* __restrict__ wv, const float* __restrict__ cosv,
    const float* __restrict__ sinv) {
    int row0 = blockIdx.x * 4;
    const float* Wm; int wrow0;
    if (row0 < 2048)      { Wm = wq; wrow0 = row0; }
    else if (row0 < 2560) { Wm = wk; wrow0 = row0 - 2048; }
    else                  { Wm = wv; wrow0 = row0 - 2560; }
    int b, r; float v;
    bool valid = gemv4_core(g_xn, Wm, DD, wrow0, threadIdx.x, &b, &r, &v);
    // RoPE on all of q,k,v: pairs are (even row, odd row) within the 4-row group.
    // threads tid and tid^1 hold the pair (same b, adjacent r).
    float vp = __shfl_xor_sync(0xffffffffu, v, 1);
    if (valid) {
        int row = wrow0 + r;
        int i = (row & 63) >> 1;
        float cc = cosv[i], ss = sinv[i];
        float res = (r & 1) ? (vp * ss + v * cc) : (v * cc - vp * ss);
        if (row0 < 2048)      g_q[(size_t)b * DD + row] = res;
        else if (row0 < 2560) g_k[(size_t)b * KVD + row] = res;
        else                  g_v[(size_t)b * KVD + row] = res;
    }
}

// ---------------- other GEMV kernels ----------------
__global__ __launch_bounds__(256) void gemv_wo_kernel(
    const float* __restrict__ wo, const float* __restrict__ x) {
    int row0 = blockIdx.x * 4;
    int b, r; float v;
    if (gemv4_core(g_attn, wo, DD, row0, threadIdx.x, &b, &r, &v)) {
        int row = row0 + r;
        g_h[(size_t)b * DD + row] = v + x[(size_t)b * DD + row];
    }
}

__global__ __launch_bounds__(256) void gemv_w1_kernel(const float* __restrict__ w1) {
    int row0 = blockIdx.x * 4;
    int b, r; float v;
    if (gemv4_core(g_hn, w1, DD, row0, threadIdx.x, &b, &r, &v)) {
        int row = row0 + r;
        g_ff1[(size_t)b * HIDDEN + row] = v / (1.0f + __expf(-v));
    }
}

__global__ __launch_bounds__(256) void gemv_w2_kernel(const float* __restrict__ w2) {
    int row0 = blockIdx.x * 4;
    int b, r; float v;
    if (gemv4_core(g_ff1, w2, HIDDEN, row0, threadIdx.x, &b, &r, &v)) {
        int row = row0 + r;
        g_ff2[(size_t)b * DD + row] = v;
    }
}

__global__ __launch_bounds__(256) void gemv_w3fin_kernel(
    const float* __restrict__ w3, float* __restrict__ out) {
    int row0 = blockIdx.x * 4;
    int b, r; float v;
    if (gemv4_core(g_hn, w3, DD, row0, threadIdx.x, &b, &r, &v)) {
        int row = row0 + r;
        out[(size_t)b * DD + row] =
            g_h[(size_t)b * DD + row] + g_ff2[(size_t)b * DD + row] + v;
    }
}

// ---------------- attention split kernel (R7 structure, NSPLIT=64) ---------
__global__ __launch_bounds__(256) void attn_split_kernel(
    const float* __restrict__ cache_k, const float* __restrict__ cache_v) {
    int blk = blockIdx.x;
    int pair = blk / NSPLIT, split = blk % NSPLIT;
    int b = pair >> 3, kv = pair & 7;
    int t0 = split * TCHUNK;
    int tid = threadIdx.x, lane = tid & 31, wid = tid >> 5;

    __shared__ float q_s[4][64];
    __shared__ float4 e_sT[TCHUNK];        // [t] -> exp(scores) for (g0..g3)
    __shared__ float red[4][8];
    __shared__ float o_part[4][4][64];     // [quarter][g][d]

    { // load + scale q
        int g = tid >> 6, d = tid & 63;
        q_s[g][d] = g_q[(size_t)b * DD + (kv * 4 + g) * 64 + d] * 0.125f;
    }
    __syncthreads();

    int c = lane & 7, p = lane >> 3;
    float qr[4][8];
#pragma unroll
    for (int g = 0; g < 4; g++)
#pragma unroll
        for (int j = 0; j < 8; j++) qr[g][j] = q_s[g][c * 8 + j];

    const float* kbase = cache_k + ((size_t)b * TSEQ * NKV + kv) * HDIM;
    const float* knew  = g_k + (size_t)(b * NKV + kv) * HDIM;

    // phase 1: exp(scores) -> smem; denominator inline
    float esum[4] = {0.f, 0.f, 0.f, 0.f};
#pragma unroll
    for (int it = 0; it < TCHUNK / 32; it++) {
        int tl = it * 32 + wid * 4 + p;
        int t = t0 + tl;
        const float* krow = (t < TSEQ - 1) ? (kbase + (size_t)t * KVD) : knew;
        const float4* k4 = (const float4*)krow;
        float4 k0 = __ldcs(k4 + c * 2);
        float4 k1 = __ldcs(k4 + c * 2 + 1);
        float kv8[8] = {k0.x, k0.y, k0.z, k0.w, k1.x, k1.y, k1.z, k1.w};
        float a0 = 0.f, a1 = 0.f, a2 = 0.f, a3 = 0.f;
#pragma unroll
        for (int j = 0; j < 8; j++) {
            a0 += qr[0][j] * kv8[j];
            a1 += qr[1][j] * kv8[j];
            a2 += qr[2][j] * kv8[j];
            a3 += qr[3][j] * kv8[j];
        }
#pragma unroll
        for (int off = 1; off <= 4; off <<= 1) {
            a0 += __shfl_xor_sync(0xffffffffu, a0, off);
            a1 += __shfl_xor_sync(0xffffffffu, a1, off);
            a2 += __shfl_xor_sync(0xffffffffu, a2, off);
            a3 += __shfl_xor_sync(0xffffffffu, a3, off);
        }
        if (c == 0) {
            float4 e;
            e.x = __expf(a0); e.y = __expf(a1);
            e.z = __expf(a2); e.w = __expf(a3);
            e_sT[tl] = e;
            esum[0] += e.x; esum[1] += e.y; esum[2] += e.z; esum[3] += e.w;
        }
    }
#pragma unroll
    for (int g = 0; g < 4; g++) {
        esum[g] = warp_sum(esum[g]);
        if (lane == 0) red[g][wid] = esum[g];
    }
    __syncthreads();
    if (tid < 4) {
        float s = 0.f;
#pragma unroll
        for (int w = 0; w < 8; w++) s += red[tid][w];
        g_pl[blk * 4 + tid] = s;
    }

    // phase 2: PV — thread (quarter, d); each V element read once per CTA
    {
        int qq = tid >> 6, d = tid & 63;
        const float* vcol = cache_v + ((size_t)b * TSEQ * NKV + kv) * HDIM + d;
        const float* vnew = g_v + (size_t)(b * NKV + kv) * HDIM + d;
        float o0 = 0.f, o1 = 0.f, o2 = 0.f, o3 = 0.f;
        int tlb = qq * (TCHUNK / 4);
#pragma unroll 8
        for (int i = 0; i < TCHUNK / 4; i++) {
            int tl = tlb + i;
            int t = t0 + tl;
            float v = (t < TSEQ - 1) ? __ldcs(vcol + (size_t)t * KVD) : *vnew;
            float4 pv = e_sT[tl];
            o0 += pv.x * v; o1 += pv.y * v; o2 += pv.z * v; o3 += pv.w * v;
        }
        o_part[qq][0][d] = o0;
        o_part[qq][1][d] = o1;
        o_part[qq][2][d] = o2;
        o_part[qq][3][d] = o3;
    }
    __syncthreads();
    {
        int g = tid >> 6, d = tid & 63;
        float sum = o_part[0][g][d] + o_part[1][g][d] +
                    o_part[2][g][d] + o_part[3][g][d];
        g_po[(size_t)blk * 256 + g * 64 + d] = sum;
    }
}

// combine split partials (pure sums)
__global__ __launch_bounds__(256) void attn_reduce_kernel() {
    int pair = blockIdx.x;
    int b = pair >> 3, kv = pair & 7;
    int tid = threadIdx.x, g = tid >> 6, d = tid & 63;
    float l = 0.f, o = 0.f;
#pragma unroll
    for (int s = 0; s < NSPLIT; s++) {
        int bs = pair * NSPLIT + s;
        l += g_pl[bs * 4 + g];
        o += g_po[(size_t)bs * 256 + g * 64 + d];
    }
    g_attn[(size_t)b * DD + (kv * 4 + g) * 64 + d] = o / l;
}

// ---------------- launch ----------------
extern "C" void kernel_launch(void* const* d_in, const int* in_sizes, int n_in,
                              void* d_out, int out_size) {
    const float* x         = (const float*)d_in[0];
    const float* freqs_cos = (const float*)d_in[1];
    const float* freqs_sin = (const float*)d_in[2];
    const float* cache_k   = (const float*)d_in[3];
    const float* cache_v   = (const float*)d_in[4];
    const float* wq_w      = (const float*)d_in[5];
    const float* wk_w      = (const float*)d_in[6];
    const float* wv_w      = (const float*)d_in[7];
    const float* wo_w      = (const float*)d_in[8];
    const float* w1_w      = (const float*)d_in[9];
    const float* w2_w      = (const float*)d_in[10];
    const float* w3_w      = (const float*)d_in[11];
    const float* attn_nw   = (const float*)d_in[12];
    const float* ffn_nw    = (const float*)d_in[13];
    float* out = (float*)d_out;

    rmsnorm_x_kernel<<<BB, 256>>>(x, attn_nw);
    gemv_qkv_kernel<<<3072 / 4, 256>>>(wq_w, wk_w, wv_w, freqs_cos, freqs_sin);
    attn_split_kernel<<<BB * NKV * NSPLIT, 256>>>(cache_k, cache_v);
    attn_reduce_kernel<<<BB * NKV, 256>>>();
    gemv_wo_kernel<<<DD / 4, 256>>>(wo_w, x);
    rmsnorm_h_kernel<<<BB, 256>>>(ffn_nw);
    gemv_w1_kernel<<<HIDDEN / 4, 256>>>(w1_w);
    gemv_w2_kernel<<<DD / 4, 256>>>(w2_w);
    gemv_w3fin_kernel<<<DD / 4, 256>>>(w3_w, out);
}

// round 10
// speedup vs baseline: 1.1246x; 1.0765x over previous
#include <cuda_runtime.h>
#include <math.h>
#include <stdint.h>

#define BB 16
#define DD 2048
#define NH 32
#define NKV 8
#define HDIM 64
#define GRP 4
#define TSEQ 4096
#define HIDDEN 5632
#define KVD 512
#define NSPLIT 32
#define TCHUNK 128

// ---------------- scratch ----------------
__device__ float g_xn[BB * DD];
__device__ float g_q[BB * DD];
__device__ float g_k[BB * KVD];
__device__ float g_v[BB * KVD];
__device__ float g_attn[BB * DD];
__device__ float g_h[BB * DD];
__device__ float g_hn[BB * DD];
__device__ float g_ff1[BB * HIDDEN];
__device__ float g_w2part[2][BB][DD];
__device__ float g_po[BB * NKV * NSPLIT * GRP * HDIM];   // 4 MB
__device__ float g_pl[BB * NKV * NSPLIT * GRP];

__device__ __forceinline__ float warp_sum(float v) {
    v += __shfl_down_sync(0xffffffffu, v, 16);
    v += __shfl_down_sync(0xffffffffu, v, 8);
    v += __shfl_down_sync(0xffffffffu, v, 4);
    v += __shfl_down_sync(0xffffffffu, v, 2);
    v += __shfl_down_sync(0xffffffffu, v, 1);
    return v;
}

// ============ staged + pipelined GEMV core ============
// CTA: 16 rows x 8 batches x KR columns. 256 thr.
// Stage: a_s[8][KR] (activations, smem). Warp w: rq=w&3 (4 rows), kh=w>>2 (K half).
// Weight loads double-buffered (depth-1 pipeline). acc[8][4].
// Valid for tid<128: batch8=tid>>4, rr=tid&15 (row offset in block).
template <int KR>
__device__ __forceinline__ bool gemv_staged(const float* __restrict__ A,
                                            const float* __restrict__ W,
                                            int K, int k0, int row0, int bh,
                                            int tid,
                                            int* pb, int* prr, float* pv) {
    extern __shared__ float dyn[];
    float* a_s = dyn;                    // 8*KR floats
    float* s_part = dyn + 8 * KR;        // [8][8][4]
    constexpr int KR4 = KR / 4;
    constexpr int PER = KR4 / 2;         // float4s per warp (K half)
    constexpr int STEPS = PER / 32;      // exact for KR in {2048, 2816}

    // stage activations: batches [bh*8, bh*8+8), cols [k0, k0+KR)
    {
        const float* Ab = A + (size_t)bh * 8 * K + k0;
        float4* a4 = (float4*)a_s;
        for (int idx = tid; idx < 2 * KR; idx += 256) {
            int b = idx / KR4, c = idx - b * KR4;
            a4[idx] = *(const float4*)(Ab + (size_t)b * K + 4 * c);
        }
    }
    __syncthreads();

    int lane = tid & 31, w = tid >> 5;
    int rq = w & 3, kh = w >> 2;
    int c0 = kh * PER;
    const float4* wp0 = (const float4*)(W + (size_t)(row0 + rq * 4 + 0) * K + k0);
    const float4* wp1 = (const float4*)(W + (size_t)(row0 + rq * 4 + 1) * K + k0);
    const float4* wp2 = (const float4*)(W + (size_t)(row0 + rq * 4 + 2) * K + k0);
    const float4* wp3 = (const float4*)(W + (size_t)(row0 + rq * 4 + 3) * K + k0);
    const float4* a4 = (const float4*)a_s;

    float acc[8][4];
#pragma unroll
    for (int b = 0; b < 8; b++)
#pragma unroll
        for (int r = 0; r < 4; r++) acc[b][r] = 0.f;

    int cc = c0 + lane;
    float4 wc0 = __ldcs(wp0 + cc), wc1 = __ldcs(wp1 + cc);
    float4 wc2 = __ldcs(wp2 + cc), wc3 = __ldcs(wp3 + cc);
#pragma unroll 2
    for (int s = 0; s < STEPS; s++) {
        float4 wn0, wn1, wn2, wn3;
        if (s + 1 < STEPS) {            // prefetch next step's weights
            wn0 = __ldcs(wp0 + cc + 32); wn1 = __ldcs(wp1 + cc + 32);
            wn2 = __ldcs(wp2 + cc + 32); wn3 = __ldcs(wp3 + cc + 32);
        }
#pragma unroll
        for (int b = 0; b < 8; b++) {
            float4 xv = a4[b * KR4 + cc];
            acc[b][0] += wc0.x * xv.x + wc0.y * xv.y + wc0.z * xv.z + wc0.w * xv.w;
            acc[b][1] += wc1.x * xv.x + wc1.y * xv.y + wc1.z * xv.z + wc1.w * xv.w;
            acc[b][2] += wc2.x * xv.x + wc2.y * xv.y + wc2.z * xv.z + wc2.w * xv.w;
            acc[b][3] += wc3.x * xv.x + wc3.y * xv.y + wc3.z * xv.z + wc3.w * xv.w;
        }
        wc0 = wn0; wc1 = wn1; wc2 = wn2; wc3 = wn3;
        cc += 32;
    }
#pragma unroll
    for (int b = 0; b < 8; b++)
#pragma unroll
        for (int r = 0; r < 4; r++) {
            float v = warp_sum(acc[b][r]);
            if (lane == 0) s_part[w * 32 + b * 4 + r] = v;
        }
    __syncthreads();
    if (tid < 128) {
        int b8 = tid >> 4, rr = tid & 15;
        int rq2 = rr >> 2, r2 = rr & 3;
        *pb = bh * 8 + b8;
        *prr = rr;
        *pv = s_part[rq2 * 32 + b8 * 4 + r2] + s_part[(4 + rq2) * 32 + b8 * 4 + r2];
        return true;
    }
    return false;
}

// ---------------- rmsnorm ----------------
__global__ void rmsnorm_x_kernel(const float* __restrict__ x,
                                 const float* __restrict__ w) {
    int b = blockIdx.x;
    const float* xr = x + (size_t)b * DD;
    float s = 0.f;
    for (int i = threadIdx.x; i < DD; i += 256) { float v = xr[i]; s += v * v; }
    for (int off = 16; off; off >>= 1) s += __shfl_xor_sync(0xffffffffu, s, off);
    __shared__ float red[8];
    int lane = threadIdx.x & 31, wid = threadIdx.x >> 5;
    if (lane == 0) red[wid] = s;
    __syncthreads();
    if (threadIdx.x == 0) {
        float t = 0.f;
#pragma unroll
        for (int i = 0; i < 8; i++) t += red[i];
        red[0] = rsqrtf(t * (1.0f / DD) + 1e-6f);
    }
    __syncthreads();
    float inv = red[0];
    float* orow = g_xn + (size_t)b * DD;
    for (int i = threadIdx.x; i < DD; i += 256) orow[i] = xr[i] * inv * w[i];
}

__global__ void rmsnorm_h_kernel(const float* __restrict__ w) {
    int b = blockIdx.x;
    const float* xr = g_h + (size_t)b * DD;
    float s = 0.f;
    for (int i = threadIdx.x; i < DD; i += 256) { float v = xr[i]; s += v * v; }
    for (int off = 16; off; off >>= 1) s += __shfl_xor_sync(0xffffffffu, s, off);
    __shared__ float red[8];
    int lane = threadIdx.x & 31, wid = threadIdx.x >> 5;
    if (lane == 0) red[wid] = s;
    __syncthreads();
    if (threadIdx.x == 0) {
        float t = 0.f;
#pragma unroll
        for (int i = 0; i < 8; i++) t += red[i];
        red[0] = rsqrtf(t * (1.0f / DD) + 1e-6f);
    }
    __syncthreads();
    float inv = red[0];
    float* orow = g_hn + (size_t)b * DD;
    for (int i = threadIdx.x; i < DD; i += 256) orow[i] = xr[i] * inv * w[i];
}

// ---------------- GEMV kernels ----------------
__global__ __launch_bounds__(256) void gemv_qkv_kernel(
    const float* __restrict__ wq, const float* __restrict__ wk,
    const float* __restrict__ wv, const float* __restrict__ cosv,
    const float* __restrict__ sinv) {
    int bi = blockIdx.x;
    int bh = bi & 1, row0 = (bi >> 1) * 16;
    const float* Wm; int wrow0;
    if (row0 < 2048)      { Wm = wq; wrow0 = row0; }
    else if (row0 < 2560) { Wm = wk; wrow0 = row0 - 2048; }
    else                  { Wm = wv; wrow0 = row0 - 2560; }
    int b, rr; float v = 0.f;
    bool valid = gemv_staged<2048>(g_xn, Wm, DD, 0, wrow0, bh, threadIdx.x,
                                   &b, &rr, &v);
    // fused RoPE: pair rows (2i, 2i+1) are held by tid and tid^1
    float vp = __shfl_xor_sync(0xffffffffu, v, 1);
    if (valid) {
        int row = wrow0 + rr;
        int i = (row & 63) >> 1;
        float cc = cosv[i], ss = sinv[i];
        float res = (rr & 1) ? (vp * ss + v * cc) : (v * cc - vp * ss);
        if (row0 < 2048)      g_q[(size_t)b * DD + row] = res;
        else if (row0 < 2560) g_k[(size_t)b * KVD + row] = res;
        else                  g_v[(size_t)b * KVD + row] = res;
    }
}

__global__ __launch_bounds__(256) void gemv_wo_kernel(
    const float* __restrict__ wo, const float* __restrict__ x) {
    int bi = blockIdx.x;
    int bh = bi & 1, row0 = (bi >> 1) * 16;
    int b, rr; float v;
    if (gemv_staged<2048>(g_attn, wo, DD, 0, row0, bh, threadIdx.x, &b, &rr, &v)) {
        int row = row0 + rr;
        g_h[(size_t)b * DD + row] = v + x[(size_t)b * DD + row];
    }
}

__global__ __launch_bounds__(256) void gemv_w1_kernel(const float* __restrict__ w1) {
    int bi = blockIdx.x;
    int bh = bi & 1, row0 = (bi >> 1) * 16;
    int b, rr; float v;
    if (gemv_staged<2048>(g_hn, w1, DD, 0, row0, bh, threadIdx.x, &b, &rr, &v)) {
        int row = row0 + rr;
        g_ff1[(size_t)b * HIDDEN + row] = v / (1.0f + __expf(-v));
    }
}

__global__ __launch_bounds__(256) void gemv_w2_kernel(const float* __restrict__ w2) {
    int bi = blockIdx.x;
    int bh = bi & 1, khB = (bi >> 1) & 1, row0 = (bi >> 2) * 16;
    int k0 = khB * (HIDDEN / 2);
    int b, rr; float v;
    if (gemv_staged<HIDDEN / 2>(g_ff1, w2, HIDDEN, k0, row0, bh, threadIdx.x,
                                &b, &rr, &v)) {
        int row = row0 + rr;
        g_w2part[khB][b][row] = v;
    }
}

__global__ __launch_bounds__(256) void gemv_w3fin_kernel(
    const float* __restrict__ w3, float* __restrict__ out) {
    int bi = blockIdx.x;
    int bh = bi & 1, row0 = (bi >> 1) * 16;
    int b, rr; float v;
    if (gemv_staged<2048>(g_hn, w3, DD, 0, row0, bh, threadIdx.x, &b, &rr, &v)) {
        int row = row0 + rr;
        out[(size_t)b * DD + row] = g_h[(size_t)b * DD + row] + v +
                                    g_w2part[0][b][row] + g_w2part[1][b][row];
    }
}

// ---------------- attention split kernel (R7, NSPLIT=32) ----------------
__global__ __launch_bounds__(256) void attn_split_kernel(
    const float* __restrict__ cache_k, const float* __restrict__ cache_v) {
    int blk = blockIdx.x;
    int pair = blk / NSPLIT, split = blk % NSPLIT;
    int b = pair >> 3, kv = pair & 7;
    int t0 = split * TCHUNK;
    int tid = threadIdx.x, lane = tid & 31, wid = tid >> 5;

    __shared__ float q_s[4][64];
    __shared__ float4 e_sT[TCHUNK];
    __shared__ float red[4][8];
    __shared__ float o_part[4][4][64];

    {
        int g = tid >> 6, d = tid & 63;
        q_s[g][d] = g_q[(size_t)b * DD + (kv * 4 + g) * 64 + d] * 0.125f;
    }
    __syncthreads();

    int c = lane & 7, p = lane >> 3;
    float qr[4][8];
#pragma unroll
    for (int g = 0; g < 4; g++)
#pragma unroll
        for (int j = 0; j < 8; j++) qr[g][j] = q_s[g][c * 8 + j];

    const float* kbase = cache_k + ((size_t)b * TSEQ * NKV + kv) * HDIM;
    const float* knew  = g_k + (size_t)(b * NKV + kv) * HDIM;

    float esum[4] = {0.f, 0.f, 0.f, 0.f};
#pragma unroll
    for (int it = 0; it < TCHUNK / 32; it++) {
        int tl = it * 32 + wid * 4 + p;
        int t = t0 + tl;
        const float* krow = (t < TSEQ - 1) ? (kbase + (size_t)t * KVD) : knew;
        const float4* k4 = (const float4*)krow;
        float4 k0 = __ldcs(k4 + c * 2);
        float4 k1 = __ldcs(k4 + c * 2 + 1);
        float kv8[8] = {k0.x, k0.y, k0.z, k0.w, k1.x, k1.y, k1.z, k1.w};
        float a0 = 0.f, a1 = 0.f, a2 = 0.f, a3 = 0.f;
#pragma unroll
        for (int j = 0; j < 8; j++) {
            a0 += qr[0][j] * kv8[j];
            a1 += qr[1][j] * kv8[j];
            a2 += qr[2][j] * kv8[j];
            a3 += qr[3][j] * kv8[j];
        }
#pragma unroll
        for (int off = 1; off <= 4; off <<= 1) {
            a0 += __shfl_xor_sync(0xffffffffu, a0, off);
            a1 += __shfl_xor_sync(0xffffffffu, a1, off);
            a2 += __shfl_xor_sync(0xffffffffu, a2, off);
            a3 += __shfl_xor_sync(0xffffffffu, a3, off);
        }
        if (c == 0) {
            float4 e;
            e.x = __expf(a0); e.y = __expf(a1);
            e.z = __expf(a2); e.w = __expf(a3);
            e_sT[tl] = e;
            esum[0] += e.x; esum[1] += e.y; esum[2] += e.z; esum[3] += e.w;
        }
    }
#pragma unroll
    for (int g = 0; g < 4; g++) {
        esum[g] = warp_sum(esum[g]);
        if (lane == 0) red[g][wid] = esum[g];
    }
    __syncthreads();
    if (tid < 4) {
        float s = 0.f;
#pragma unroll
        for (int w = 0; w < 8; w++) s += red[tid][w];
        g_pl[blk * 4 + tid] = s;
    }

    {
        int qq = tid >> 6, d = tid & 63;
        const float* vcol = cache_v + ((size_t)b * TSEQ * NKV + kv) * HDIM + d;
        const float* vnew = g_v + (size_t)(b * NKV + kv) * HDIM + d;
        float o0 = 0.f, o1 = 0.f, o2 = 0.f, o3 = 0.f;
        int tlb = qq * (TCHUNK / 4);
#pragma unroll 8
        for (int i = 0; i < TCHUNK / 4; i++) {
            int tl = tlb + i;
            int t = t0 + tl;
            float v = (t < TSEQ - 1) ? __ldcs(vcol + (size_t)t * KVD) : *vnew;
            float4 pv = e_sT[tl];
            o0 += pv.x * v; o1 += pv.y * v; o2 += pv.z * v; o3 += pv.w * v;
        }
        o_part[qq][0][d] = o0;
        o_part[qq][1][d] = o1;
        o_part[qq][2][d] = o2;
        o_part[qq][3][d] = o3;
    }
    __syncthreads();
    {
        int g = tid >> 6, d = tid & 63;
        float sum = o_part[0][g][d] + o_part[1][g][d] +
                    o_part[2][g][d] + o_part[3][g][d];
        g_po[(size_t)blk * 256 + g * 64 + d] = sum;
    }
}

__global__ __launch_bounds__(256) void attn_reduce_kernel() {
    int pair = blockIdx.x;
    int b = pair >> 3, kv = pair & 7;
    int tid = threadIdx.x, g = tid >> 6, d = tid & 63;
    float l = 0.f, o = 0.f;
#pragma unroll
    for (int s = 0; s < NSPLIT; s++) {
        int bs = pair * NSPLIT + s;
        l += g_pl[bs * 4 + g];
        o += g_po[(size_t)bs * 256 + g * 64 + d];
    }
    g_attn[(size_t)b * DD + (kv * 4 + g) * 64 + d] = o / l;
}

// ---------------- launch ----------------
extern "C" void kernel_launch(void* const* d_in, const int* in_sizes, int n_in,
                              void* d_out, int out_size) {
    const float* x         = (const float*)d_in[0];
    const float* freqs_cos = (const float*)d_in[1];
    const float* freqs_sin = (const float*)d_in[2];
    const float* cache_k   = (const float*)d_in[3];
    const float* cache_v   = (const float*)d_in[4];
    const float* wq_w      = (const float*)d_in[5];
    const float* wk_w      = (const float*)d_in[6];
    const float* wv_w      = (const float*)d_in[7];
    const float* wo_w      = (const float*)d_in[8];
    const float* w1_w      = (const float*)d_in[9];
    const float* w2_w      = (const float*)d_in[10];
    const float* w3_w      = (const float*)d_in[11];
    const float* attn_nw   = (const float*)d_in[12];
    const float* ffn_nw    = (const float*)d_in[13];
    float* out = (float*)d_out;

    const int SMEM_STD = (8 * 2048 + 256) * 4;          // 66560
    const int SMEM_W2  = (8 * (HIDDEN / 2) + 256) * 4;  // 91136
    cudaFuncSetAttribute(gemv_qkv_kernel,  cudaFuncAttributeMaxDynamicSharedMemorySize, SMEM_STD);
    cudaFuncSetAttribute(gemv_wo_kernel,   cudaFuncAttributeMaxDynamicSharedMemorySize, SMEM_STD);
    cudaFuncSetAttribute(gemv_w1_kernel,   cudaFuncAttributeMaxDynamicSharedMemorySize, SMEM_STD);
    cudaFuncSetAttribute(gemv_w2_kernel,   cudaFuncAttributeMaxDynamicSharedMemorySize, SMEM_W2);
    cudaFuncSetAttribute(gemv_w3fin_kernel,cudaFuncAttributeMaxDynamicSharedMemorySize, SMEM_STD);

    rmsnorm_x_kernel<<<BB, 256>>>(x, attn_nw);
    gemv_qkv_kernel<<<(3072 / 16) * 2, 256, SMEM_STD>>>(wq_w, wk_w, wv_w,
                                                        freqs_cos, freqs_sin);
    attn_split_kernel<<<BB * NKV * NSPLIT, 256>>>(cache_k, cache_v);
    attn_reduce_kernel<<<BB * NKV, 256>>>();
    gemv_wo_kernel<<<(DD / 16) * 2, 256, SMEM_STD>>>(wo_w, x);
    rmsnorm_h_kernel<<<BB, 256>>>(ffn_nw);
    gemv_w1_kernel<<<(HIDDEN / 16) * 2, 256, SMEM_STD>>>(w1_w);
    gemv_w2_kernel<<<(DD / 16) * 4, 256, SMEM_W2>>>(w2_w);
    gemv_w3fin_kernel<<<(DD / 16) * 2, 256, SMEM_STD>>>(w3_w, out);
}